// round 2
// baseline (speedup 1.0000x reference)
// NodeContrastiveLoss — fused bf16 mma.sync (HMMA) GEMM + streaming log-sum-exp.
// (tcgen05 is ptxas-rejected on this build's compute_103 virtual arch, so we use
//  base-ISA m16n8k16 bf16 mma with register accumulators + fused exp2 epilogue.)
//
// loss = mean_i[ (1 - dot(z1n_i,z2n_i))/tau
//              + ln( sum_j exp((d12_ij-1)/tau) + sum_{j!=i} exp((d11_ij-1)/tau) ) ]
//
// Kernel 1: row L2-normalize -> bf16 scratch.
// Kernel 2: 128 CTAs; A-tile (128 rows of z1n) resident in registers as mma
//           fragments; stream 256 B-tiles (z2n then z1n) through a 2-stage
//           cp.async pipeline; per-thread row accumulators across all tiles.
// Kernel 3: reduce 128 block sums.
#include <cuda_runtime.h>
#include <cuda_bf16.h>
#include <cstdint>
#include <cstddef>

#define N_ROWS 16384
#define DIM    128
#define TILE   128
#define NTILES 256   // tiles 0..127 = z2 pass (d12), 128..255 = z1 pass (d11)

#define INV_TAU 14.285714285714286f
#define K1F     20.609929155556620f   // log2(e)/tau
#define LN2F    0.6931471805599453f

static __device__ __nv_bfloat16 g_z1n[(size_t)N_ROWS * DIM];
static __device__ __nv_bfloat16 g_z2n[(size_t)N_ROWS * DIM];
static __device__ float        g_bsum[128];

// ---------------- helpers ----------------
__device__ __forceinline__ uint32_t smem_u32(const void* p) {
    uint32_t r;
    asm("{ .reg .u64 t; cvta.to.shared.u64 t, %1; cvt.u32.u64 %0, t; }" : "=r"(r) : "l"(p));
    return r;
}
__device__ __forceinline__ void cp_async16(uint32_t dst, const void* src) {
    asm volatile("cp.async.cg.shared.global [%0], [%1], 16;" :: "r"(dst), "l"(src) : "memory");
}
__device__ __forceinline__ void cp_commit() { asm volatile("cp.async.commit_group;" ::: "memory"); }
template <int N>
__device__ __forceinline__ void cp_wait() { asm volatile("cp.async.wait_group %0;" :: "n"(N) : "memory"); }

__device__ __forceinline__ void ldsm4(uint32_t r[4], uint32_t addr) {
    asm volatile("ldmatrix.sync.aligned.m8n8.x4.shared.b16 {%0,%1,%2,%3}, [%4];"
                 : "=r"(r[0]), "=r"(r[1]), "=r"(r[2]), "=r"(r[3]) : "r"(addr));
}
__device__ __forceinline__ void mma16816(float c[4], const uint32_t a[4], uint32_t b0, uint32_t b1) {
    asm volatile(
        "mma.sync.aligned.m16n8k16.row.col.f32.bf16.bf16.f32 "
        "{%0,%1,%2,%3}, {%4,%5,%6,%7}, {%8,%9}, {%0,%1,%2,%3};"
        : "+f"(c[0]), "+f"(c[1]), "+f"(c[2]), "+f"(c[3])
        : "r"(a[0]), "r"(a[1]), "r"(a[2]), "r"(a[3]), "r"(b0), "r"(b1));
}
__device__ __forceinline__ float ex2f(float x) { float y; asm("ex2.approx.f32 %0, %1;" : "=f"(y) : "f"(x)); return y; }
__device__ __forceinline__ float lg2f(float x) { float y; asm("lg2.approx.f32 %0, %1;" : "=f"(y) : "f"(x)); return y; }

// Tile layout in SMEM: 128 rows x 256 B (16 chunks of 16 B), XOR swizzle so
// ldmatrix (8 rows, same chunk) hits 8 distinct 16B bank segments.
__device__ __forceinline__ uint32_t swz(int row, int c) {
    return (uint32_t)(row * 256 + ((c ^ (row & 7)) << 4));
}

// ---------------- SMEM layout (dynamic, 96 KB) ----------------
#define SMEM_A  0
#define SMEM_B0 32768
#define SMEM_B1 65536
#define SMEM_TOTAL 98304

// ---------------- kernel 1: normalize ----------------
__global__ void __launch_bounds__(256) norm_kernel(const float* __restrict__ z1,
                                                   const float* __restrict__ z2) {
    int gw = blockIdx.x * 8 + (threadIdx.x >> 5);
    int lane = threadIdx.x & 31;
#pragma unroll
    for (int s = 0; s < 2; s++) {
        const float* src = s ? z2 : z1;
        __nv_bfloat16* dst = s ? g_z2n : g_z1n;
        float4 v = ((const float4*)(src + (size_t)gw * DIM))[lane];
        float ss = v.x * v.x + v.y * v.y + v.z * v.z + v.w * v.w;
#pragma unroll
        for (int o = 16; o; o >>= 1) ss += __shfl_xor_sync(0xffffffffu, ss, o);
        float inv = rsqrtf(ss);
        __nv_bfloat162 a = __floats2bfloat162_rn(v.x * inv, v.y * inv);
        __nv_bfloat162 b = __floats2bfloat162_rn(v.z * inv, v.w * inv);
        __nv_bfloat162* d2 = (__nv_bfloat162*)(dst + (size_t)gw * DIM + lane * 4);
        d2[0] = a; d2[1] = b;
    }
}

// ---------------- tile consumer ----------------
// MODE: 0 plain, 1 = z1z2 diag tile (capture pos), 2 = z1z1 diag tile (mask diag)
template <int MODE>
__device__ __forceinline__ void consume_tile(
    uint32_t sB, const uint32_t a[8][4], int brow_off, int bch,
    int r0, int c0base,
    float& racc0, float& racc1, float& pos0, float& pos1)
{
#pragma unroll
    for (int nb = 0; nb < 8; nb++) {
        float clo[4] = {0.f, 0.f, 0.f, 0.f};
        float chi[4] = {0.f, 0.f, 0.f, 0.f};
        const int nbase = nb * 16;
#pragma unroll
        for (int ks = 0; ks < 8; ks++) {
            uint32_t b[4];
            ldsm4(b, sB + swz(nbase + brow_off, ks * 2 + bch));
            mma16816(clo, a[ks], b[0], b[1]);
            mma16816(chi, a[ks], b[2], b[3]);
        }
        // epilogue: 8 values -> exp2 -> row accumulators
#pragma unroll
        for (int i = 0; i < 4; i++) {
            // clo[i]: row = r0 + 8*(i>>1), col = nbase + c0base + (i&1)
            // chi[i]: same row, col + 8
            const int jl = nbase + c0base + (i & 1);
            const int jh = jl + 8;
            const int rr = r0 + 8 * (i >> 1);
            float xl = clo[i], xh = chi[i];
            float el = ex2f(fmaf(xl, K1F, -K1F));
            float eh = ex2f(fmaf(xh, K1F, -K1F));
            if (MODE == 1) {
                if (jl == rr) { if (i >> 1) pos1 = xl; else pos0 = xl; }
                if (jh == rr) { if (i >> 1) pos1 = xh; else pos0 = xh; }
            }
            if (MODE == 2) {
                if (jl == rr) el = 0.f;
                if (jh == rr) eh = 0.f;
            }
            float e = el + eh;
            if (i >> 1) racc1 += e; else racc0 += e;
        }
    }
}

// ---------------- kernel 2: main fused loop ----------------
__global__ void __launch_bounds__(256, 1) ncl_main_kernel() {
    extern __shared__ char smem[];
    const uint32_t sb = smem_u32(smem);
    const int tid = threadIdx.x;
    const int wid = tid >> 5;
    const int lane = tid & 31;
    const int bx = blockIdx.x;
    const int m0 = bx * TILE;

    // per-thread gmem->smem copy slots: row = tid/2, 8 chunks starting at (tid&1)*8
    const int crow = tid >> 1;
    const int cb = (tid & 1) * 8;
    uint32_t dsto[8];
#pragma unroll
    for (int c = 0; c < 8; c++) dsto[c] = swz(crow, cb + c);

    // load A tile (z1n rows m0..m0+127) and B tile 0 (z2n rows 0..127)
    {
        const char* srcA = (const char*)g_z1n + ((size_t)(m0 + crow) * DIM + cb * 8) * 2;
        const char* srcB = (const char*)g_z2n + ((size_t)crow * DIM + cb * 8) * 2;
#pragma unroll
        for (int c = 0; c < 8; c++) {
            cp_async16(sb + SMEM_A + dsto[c], srcA + c * 16);
            cp_async16(sb + SMEM_B0 + dsto[c], srcB + c * 16);
        }
    }
    cp_commit(); cp_wait<0>();
    __syncthreads();

    // A fragments -> registers (kept for whole kernel)
    uint32_t a[8][4];
    {
        const int arow = wid * 16 + (lane & 15);
        const int ach = lane >> 4;
#pragma unroll
        for (int ks = 0; ks < 8; ks++)
            ldsm4(a[ks], sb + SMEM_A + swz(arow, ks * 2 + ach));
    }

    // B ldmatrix per-thread address pieces
    const int brow_off = (lane & 7) + ((lane & 16) >> 1); // (l%8) + (l>=16 ? 8 : 0)
    const int bch = (lane >> 3) & 1;

    // accumulator coordinates
    const int r0 = wid * 16 + (lane >> 2);   // rows r0 and r0+8
    const int c0base = (lane & 3) * 2;

    float racc0 = 0.f, racc1 = 0.f, pos0 = 0.f, pos1 = 0.f;

    for (int t = 0; t < NTILES; t++) {
        // prefetch tile t+1 into the other stage
        if (t + 1 < NTILES) {
            const int tt = t + 1;
            const char* src = (const char*)((tt & 128) ? g_z1n : g_z2n)
                            + ((size_t)((tt & 127) * TILE + crow) * DIM + cb * 8) * 2;
            const uint32_t dst = sb + ((tt & 1) ? SMEM_B1 : SMEM_B0);
#pragma unroll
            for (int c = 0; c < 8; c++) cp_async16(dst + dsto[c], src + c * 16);
            cp_commit();
            cp_wait<1>();
        } else {
            cp_wait<0>();
        }
        __syncthreads();

        const uint32_t sB = sb + ((t & 1) ? SMEM_B1 : SMEM_B0);
        if (t == bx)
            consume_tile<1>(sB, a, brow_off, bch, r0, c0base, racc0, racc1, pos0, pos1);
        else if (t == bx + 128)
            consume_tile<2>(sB, a, brow_off, bch, r0, c0base, racc0, racc1, pos0, pos1);
        else
            consume_tile<0>(sB, a, brow_off, bch, r0, c0base, racc0, racc1, pos0, pos1);
        __syncthreads();
    }

    // ---- reduction: quad (lanes sharing a row) -> per-row loss -> block sum ----
    racc0 += __shfl_xor_sync(0xffffffffu, racc0, 1);
    racc0 += __shfl_xor_sync(0xffffffffu, racc0, 2);
    racc1 += __shfl_xor_sync(0xffffffffu, racc1, 1);
    racc1 += __shfl_xor_sync(0xffffffffu, racc1, 2);
    pos0  += __shfl_xor_sync(0xffffffffu, pos0, 1);
    pos0  += __shfl_xor_sync(0xffffffffu, pos0, 2);
    pos1  += __shfl_xor_sync(0xffffffffu, pos1, 1);
    pos1  += __shfl_xor_sync(0xffffffffu, pos1, 2);

    float wsum = 0.f;
    if ((lane & 3) == 0) {
        float l0 = (1.0f - pos0) * INV_TAU + lg2f(racc0) * LN2F;
        float l1 = (1.0f - pos1) * INV_TAU + lg2f(racc1) * LN2F;
        wsum = l0 + l1;
    }
#pragma unroll
    for (int o = 16; o; o >>= 1) wsum += __shfl_xor_sync(0xffffffffu, wsum, o);

    float* red = (float*)smem;   // reuse A region (post-loop, after barrier)
    if (lane == 0) red[wid] = wsum;
    __syncthreads();
    if (tid == 0) {
        float s = 0.f;
#pragma unroll
        for (int w = 0; w < 8; w++) s += red[w];
        g_bsum[bx] = s;
    }
}

// ---------------- kernel 3: finalize ----------------
__global__ void finalize_kernel(float* out) {
    int lane = threadIdx.x;
    float s = g_bsum[lane] + g_bsum[lane + 32] + g_bsum[lane + 64] + g_bsum[lane + 96];
#pragma unroll
    for (int o = 16; o; o >>= 1) s += __shfl_xor_sync(0xffffffffu, s, o);
    if (lane == 0) out[0] = s * (1.0f / (float)N_ROWS);
}

// ---------------- launch ----------------
extern "C" void kernel_launch(void* const* d_in, const int* in_sizes, int n_in,
                              void* d_out, int out_size) {
    const float* z1 = (const float*)d_in[0];
    const float* z2 = (const float*)d_in[1];
    float* out = (float*)d_out;
    (void)in_sizes; (void)n_in; (void)out_size;

    cudaFuncSetAttribute(ncl_main_kernel, cudaFuncAttributeMaxDynamicSharedMemorySize, SMEM_TOTAL);

    norm_kernel<<<N_ROWS / 8, 256>>>(z1, z2);
    ncl_main_kernel<<<N_ROWS / TILE, 256, SMEM_TOTAL>>>();
    finalize_kernel<<<1, 32>>>(out);
}

// round 3
// speedup vs baseline: 1.0004x; 1.0004x over previous
// NodeContrastiveLoss — fused bf16 mma.sync (HMMA) GEMM + streaming log-sum-exp.
// R3: break MMA accumulator RAW chains (4 independent chains/warp, K-outer in
// nb-pairs), software-pipeline ldsm one K-step ahead, interleave exp2 epilogue
// per nb-pair so MUFU overlaps tensor drain.
#include <cuda_runtime.h>
#include <cuda_bf16.h>
#include <cstdint>
#include <cstddef>

#define N_ROWS 16384
#define DIM    128
#define TILE   128
#define NTILES 256   // tiles 0..127 = z2 pass (d12), 128..255 = z1 pass (d11)

#define INV_TAU 14.285714285714286f
#define K1F     20.609929155556620f   // log2(e)/tau
#define LN2F    0.6931471805599453f

static __device__ __nv_bfloat16 g_z1n[(size_t)N_ROWS * DIM];
static __device__ __nv_bfloat16 g_z2n[(size_t)N_ROWS * DIM];
static __device__ float        g_bsum[128];

// ---------------- helpers ----------------
__device__ __forceinline__ uint32_t smem_u32(const void* p) {
    uint32_t r;
    asm("{ .reg .u64 t; cvta.to.shared.u64 t, %1; cvt.u32.u64 %0, t; }" : "=r"(r) : "l"(p));
    return r;
}
__device__ __forceinline__ void cp_async16(uint32_t dst, const void* src) {
    asm volatile("cp.async.cg.shared.global [%0], [%1], 16;" :: "r"(dst), "l"(src) : "memory");
}
__device__ __forceinline__ void cp_commit() { asm volatile("cp.async.commit_group;" ::: "memory"); }
template <int N>
__device__ __forceinline__ void cp_wait() { asm volatile("cp.async.wait_group %0;" :: "n"(N) : "memory"); }

__device__ __forceinline__ void ldsm4(uint32_t r[4], uint32_t addr) {
    asm volatile("ldmatrix.sync.aligned.m8n8.x4.shared.b16 {%0,%1,%2,%3}, [%4];"
                 : "=r"(r[0]), "=r"(r[1]), "=r"(r[2]), "=r"(r[3]) : "r"(addr));
}
__device__ __forceinline__ void mma16816(float c[4], const uint32_t a[4], uint32_t b0, uint32_t b1) {
    asm volatile(
        "mma.sync.aligned.m16n8k16.row.col.f32.bf16.bf16.f32 "
        "{%0,%1,%2,%3}, {%4,%5,%6,%7}, {%8,%9}, {%0,%1,%2,%3};"
        : "+f"(c[0]), "+f"(c[1]), "+f"(c[2]), "+f"(c[3])
        : "r"(a[0]), "r"(a[1]), "r"(a[2]), "r"(a[3]), "r"(b0), "r"(b1));
}
__device__ __forceinline__ float ex2f(float x) { float y; asm("ex2.approx.f32 %0, %1;" : "=f"(y) : "f"(x)); return y; }
__device__ __forceinline__ float lg2f(float x) { float y; asm("lg2.approx.f32 %0, %1;" : "=f"(y) : "f"(x)); return y; }

// Tile layout in SMEM: 128 rows x 256 B (16 chunks of 16 B), XOR swizzle so
// ldmatrix (8 rows, same chunk) hits 8 distinct 16B bank segments.
__device__ __forceinline__ uint32_t swz(int row, int c) {
    return (uint32_t)(row * 256 + ((c ^ (row & 7)) << 4));
}

// ---------------- SMEM layout (dynamic, 96 KB) ----------------
#define SMEM_A  0
#define SMEM_B0 32768
#define SMEM_B1 65536
#define SMEM_TOTAL 98304

// ---------------- kernel 1: normalize ----------------
__global__ void __launch_bounds__(256) norm_kernel(const float* __restrict__ z1,
                                                   const float* __restrict__ z2) {
    int gw = blockIdx.x * 8 + (threadIdx.x >> 5);
    int lane = threadIdx.x & 31;
#pragma unroll
    for (int s = 0; s < 2; s++) {
        const float* src = s ? z2 : z1;
        __nv_bfloat16* dst = s ? g_z2n : g_z1n;
        float4 v = ((const float4*)(src + (size_t)gw * DIM))[lane];
        float ss = v.x * v.x + v.y * v.y + v.z * v.z + v.w * v.w;
#pragma unroll
        for (int o = 16; o; o >>= 1) ss += __shfl_xor_sync(0xffffffffu, ss, o);
        float inv = rsqrtf(ss);
        __nv_bfloat162 a = __floats2bfloat162_rn(v.x * inv, v.y * inv);
        __nv_bfloat162 b = __floats2bfloat162_rn(v.z * inv, v.w * inv);
        __nv_bfloat162* d2 = (__nv_bfloat162*)(dst + (size_t)gw * DIM + lane * 4);
        d2[0] = a; d2[1] = b;
    }
}

// ---------------- epilogue for one nb block (16 cols, 8 values) ----------------
// MODE: 0 plain, 1 = z1z2 diag tile (capture pos), 2 = z1z1 diag tile (mask diag)
template <int MODE>
__device__ __forceinline__ void epi_nb(
    int nbase, const float clo[4], const float chi[4],
    int r0, int c0base,
    float& racc0, float& racc1, float& pos0, float& pos1)
{
#pragma unroll
    for (int i = 0; i < 4; i++) {
        const int jl = nbase + c0base + (i & 1);
        const int jh = jl + 8;
        const int rr = r0 + 8 * (i >> 1);
        float xl = clo[i], xh = chi[i];
        float el = ex2f(fmaf(xl, K1F, -K1F));
        float eh = ex2f(fmaf(xh, K1F, -K1F));
        if (MODE == 1) {
            if (jl == rr) { if (i >> 1) pos1 = xl; else pos0 = xl; }
            if (jh == rr) { if (i >> 1) pos1 = xh; else pos0 = xh; }
        }
        if (MODE == 2) {
            if (jl == rr) el = 0.f;
            if (jh == rr) eh = 0.f;
        }
        float e = el + eh;
        if (i >> 1) racc1 += e; else racc0 += e;
    }
}

// ---------------- tile consumer ----------------
template <int MODE>
__device__ __forceinline__ void consume_tile(
    uint32_t sB, const uint32_t a[8][4], int brow_off, int bch,
    int r0, int c0base,
    float& racc0, float& racc1, float& pos0, float& pos1)
{
    const int rx = brow_off & 7;
#pragma unroll
    for (int nbp = 0; nbp < 4; nbp++) {
        const int nb0 = nbp * 2, nb1 = nb0 + 1;
        const uint32_t base0 = sB + (uint32_t)((nb0 * 16 + brow_off) * 256);
        const uint32_t base1 = sB + (uint32_t)((nb1 * 16 + brow_off) * 256);

        uint32_t b0[2][4], b1[2][4];
        ldsm4(b0[0], base0 + (uint32_t)((bch ^ rx) << 4));
        ldsm4(b1[0], base1 + (uint32_t)((bch ^ rx) << 4));

        float c00[4] = {0.f, 0.f, 0.f, 0.f};
        float c01[4] = {0.f, 0.f, 0.f, 0.f};
        float c10[4] = {0.f, 0.f, 0.f, 0.f};
        float c11[4] = {0.f, 0.f, 0.f, 0.f};

#pragma unroll
        for (int ks = 0; ks < 8; ks++) {
            const int cur = ks & 1, nxt = cur ^ 1;
            if (ks < 7) {
                const uint32_t co = (uint32_t)((((ks + 1) * 2 + bch) ^ rx) << 4);
                ldsm4(b0[nxt], base0 + co);
                ldsm4(b1[nxt], base1 + co);
            }
            mma16816(c00, a[ks], b0[cur][0], b0[cur][1]);
            mma16816(c01, a[ks], b0[cur][2], b0[cur][3]);
            mma16816(c10, a[ks], b1[cur][0], b1[cur][1]);
            mma16816(c11, a[ks], b1[cur][2], b1[cur][3]);
        }
        // epilogue (MUFU/fma) — non-volatile asm lets the compiler overlap this
        // with the next nb-pair's tensor work
        epi_nb<MODE>(nb0 * 16, c00, c01, r0, c0base, racc0, racc1, pos0, pos1);
        epi_nb<MODE>(nb1 * 16, c10, c11, r0, c0base, racc0, racc1, pos0, pos1);
    }
}

// ---------------- kernel 2: main fused loop ----------------
__global__ void __launch_bounds__(256, 1) ncl_main_kernel() {
    extern __shared__ char smem[];
    const uint32_t sb = smem_u32(smem);
    const int tid = threadIdx.x;
    const int wid = tid >> 5;
    const int lane = tid & 31;
    const int bx = blockIdx.x;
    const int m0 = bx * TILE;

    // per-thread gmem->smem copy slots: row = tid/2, 8 chunks starting at (tid&1)*8
    const int crow = tid >> 1;
    const int cb = (tid & 1) * 8;
    uint32_t dsto[8];
#pragma unroll
    for (int c = 0; c < 8; c++) dsto[c] = swz(crow, cb + c);

    // load A tile (z1n rows m0..m0+127) and B tile 0 (z2n rows 0..127)
    {
        const char* srcA = (const char*)g_z1n + ((size_t)(m0 + crow) * DIM + cb * 8) * 2;
        const char* srcB = (const char*)g_z2n + ((size_t)crow * DIM + cb * 8) * 2;
#pragma unroll
        for (int c = 0; c < 8; c++) {
            cp_async16(sb + SMEM_A + dsto[c], srcA + c * 16);
            cp_async16(sb + SMEM_B0 + dsto[c], srcB + c * 16);
        }
    }
    cp_commit(); cp_wait<0>();
    __syncthreads();

    // A fragments -> registers (kept for whole kernel)
    uint32_t a[8][4];
    {
        const int arow = wid * 16 + (lane & 15);
        const int ach = lane >> 4;
#pragma unroll
        for (int ks = 0; ks < 8; ks++)
            ldsm4(a[ks], sb + SMEM_A + swz(arow, ks * 2 + ach));
    }

    // B ldmatrix per-thread address pieces
    const int brow_off = (lane & 7) + ((lane & 16) >> 1); // (l%8) + (l>=16 ? 8 : 0)
    const int bch = (lane >> 3) & 1;

    // accumulator coordinates
    const int r0 = wid * 16 + (lane >> 2);   // rows r0 and r0+8
    const int c0base = (lane & 3) * 2;

    float racc0 = 0.f, racc1 = 0.f, pos0 = 0.f, pos1 = 0.f;

    for (int t = 0; t < NTILES; t++) {
        // prefetch tile t+1 into the other stage
        if (t + 1 < NTILES) {
            const int tt = t + 1;
            const char* src = (const char*)((tt & 128) ? g_z1n : g_z2n)
                            + ((size_t)((tt & 127) * TILE + crow) * DIM + cb * 8) * 2;
            const uint32_t dst = sb + ((tt & 1) ? SMEM_B1 : SMEM_B0);
#pragma unroll
            for (int c = 0; c < 8; c++) cp_async16(dst + dsto[c], src + c * 16);
            cp_commit();
            cp_wait<1>();
        } else {
            cp_wait<0>();
        }
        __syncthreads();

        const uint32_t sB = sb + ((t & 1) ? SMEM_B1 : SMEM_B0);
        if (t == bx)
            consume_tile<1>(sB, a, brow_off, bch, r0, c0base, racc0, racc1, pos0, pos1);
        else if (t == bx + 128)
            consume_tile<2>(sB, a, brow_off, bch, r0, c0base, racc0, racc1, pos0, pos1);
        else
            consume_tile<0>(sB, a, brow_off, bch, r0, c0base, racc0, racc1, pos0, pos1);
        __syncthreads();
    }

    // ---- reduction: quad (lanes sharing a row) -> per-row loss -> block sum ----
    racc0 += __shfl_xor_sync(0xffffffffu, racc0, 1);
    racc0 += __shfl_xor_sync(0xffffffffu, racc0, 2);
    racc1 += __shfl_xor_sync(0xffffffffu, racc1, 1);
    racc1 += __shfl_xor_sync(0xffffffffu, racc1, 2);
    pos0  += __shfl_xor_sync(0xffffffffu, pos0, 1);
    pos0  += __shfl_xor_sync(0xffffffffu, pos0, 2);
    pos1  += __shfl_xor_sync(0xffffffffu, pos1, 1);
    pos1  += __shfl_xor_sync(0xffffffffu, pos1, 2);

    float wsum = 0.f;
    if ((lane & 3) == 0) {
        float l0 = (1.0f - pos0) * INV_TAU + lg2f(racc0) * LN2F;
        float l1 = (1.0f - pos1) * INV_TAU + lg2f(racc1) * LN2F;
        wsum = l0 + l1;
    }
#pragma unroll
    for (int o = 16; o; o >>= 1) wsum += __shfl_xor_sync(0xffffffffu, wsum, o);

    float* red = (float*)smem;   // reuse A region (post-loop, after barrier)
    if (lane == 0) red[wid] = wsum;
    __syncthreads();
    if (tid == 0) {
        float s = 0.f;
#pragma unroll
        for (int w = 0; w < 8; w++) s += red[w];
        g_bsum[bx] = s;
    }
}

// ---------------- kernel 3: finalize ----------------
__global__ void finalize_kernel(float* out) {
    int lane = threadIdx.x;
    float s = g_bsum[lane] + g_bsum[lane + 32] + g_bsum[lane + 64] + g_bsum[lane + 96];
#pragma unroll
    for (int o = 16; o; o >>= 1) s += __shfl_xor_sync(0xffffffffu, s, o);
    if (lane == 0) out[0] = s * (1.0f / (float)N_ROWS);
}

// ---------------- launch ----------------
extern "C" void kernel_launch(void* const* d_in, const int* in_sizes, int n_in,
                              void* d_out, int out_size) {
    const float* z1 = (const float*)d_in[0];
    const float* z2 = (const float*)d_in[1];
    float* out = (float*)d_out;
    (void)in_sizes; (void)n_in; (void)out_size;

    cudaFuncSetAttribute(ncl_main_kernel, cudaFuncAttributeMaxDynamicSharedMemorySize, SMEM_TOTAL);

    norm_kernel<<<N_ROWS / 8, 256>>>(z1, z2);
    ncl_main_kernel<<<N_ROWS / TILE, 256, SMEM_TOTAL>>>();
    finalize_kernel<<<1, 32>>>(out);
}